// round 5
// baseline (speedup 1.0000x reference)
#include <cuda_runtime.h>

#define BB 256
#define LL 500
#define EE 300
#define NROWS (BB * LL)          // 128000
#define NWV 18                   // 3 + 5 + 7 conv rows + 3 cw rows

#define TILE_ROWS 64
#define EK 60                    // e-chunk (300 = 5 * 60)
#define NCHUNK 5
#define XS_STRIDE 64             // words per row in x smem (swizzle space)
#define WS_STRIDE 60             // words per row in w smem
#define THREADS1 64

// 9.2 MB scratch for the 18 dot products per row (device global: no allocs allowed)
__device__ float g_Q[(size_t)NROWS * NWV];

__device__ __forceinline__ unsigned long long ffma2(unsigned long long a,
                                                    unsigned long long b,
                                                    unsigned long long c) {
    unsigned long long d;
    asm("fma.rn.f32x2 %0, %1, %2, %3;" : "=l"(d) : "l"(a), "l"(b), "l"(c));
    return d;
}

// ---------------------------------------------------------------------------
// Kernel 1: Q[row][0:18] = x[row] . W[wv]   (tall-skinny GEMM, f32x2 FMAs)
//   wv 0-2  : aw3 rows,  3-7 : aw5 rows,  8-14 : aw7 rows, 15/16/17 : cw3/5/7
// ---------------------------------------------------------------------------
__global__ __launch_bounds__(THREADS1) void dots_kernel(
    const float* __restrict__ x,
    const float* __restrict__ aw3, const float* __restrict__ aw5,
    const float* __restrict__ aw7,
    const float* __restrict__ cw3, const float* __restrict__ cw5,
    const float* __restrict__ cw7)
{
    __shared__ __align__(16) float xs[TILE_ROWS * XS_STRIDE];  // 16 KB, swizzled
    __shared__ __align__(16) float ws[NWV * WS_STRIDE];        // 4.2 KB

    const int tid  = threadIdx.x;
    const int rgrp = tid & 31;       // lane -> row group
    const int cgrp = tid >> 5;       // warp -> wv group (0: wv 0-8, 1: wv 9-17)
    const int rowBase = blockIdx.x * TILE_ROWS;

    unsigned long long acc[2][9];
    #pragma unroll
    for (int i = 0; i < 2; i++)
        #pragma unroll
        for (int c = 0; c < 9; c++) acc[i][c] = 0ull;

    const float* xbase = x + (size_t)rowBase * EE;

    for (int ck = 0; ck < NCHUNK; ck++) {
        const int ce = ck * EK;

        // ---- load x chunk: 64 rows x 60 floats (15 float4/row), swizzled store
        #pragma unroll
        for (int t = tid; t < TILE_ROWS * 15; t += THREADS1) {
            int row = t / 15, quad = t % 15;
            float4 v = *reinterpret_cast<const float4*>(
                xbase + (size_t)row * EE + ce + quad * 4);
            int r4 = row & 15;
            int s0 = (2 * quad) ^ r4;       // 8B-slot swizzle (bank-conflict free)
            int s1 = (2 * quad + 1) ^ r4;
            float2* b2 = reinterpret_cast<float2*>(&xs[row * XS_STRIDE]);
            b2[s0] = make_float2(v.x, v.y);
            b2[s1] = make_float2(v.z, v.w);
        }

        // ---- load w chunk: 18 rows x 60 floats
        #pragma unroll
        for (int t = tid; t < NWV * 15; t += THREADS1) {
            int wr = t / 15, quad = t % 15;
            const float* src;
            if (wr < 3)       src = aw3 + wr * EE;
            else if (wr < 8)  src = aw5 + (wr - 3) * EE;
            else if (wr < 15) src = aw7 + (wr - 8) * EE;
            else              src = (wr == 15) ? cw3 : (wr == 16) ? cw5 : cw7;
            float4 v = *reinterpret_cast<const float4*>(src + ce + quad * 4);
            *reinterpret_cast<float4*>(&ws[wr * WS_STRIDE + quad * 4]) = v;
        }
        __syncthreads();

        // ---- compute: per 4-e step: 18 FFMA2 per (i) row pair-set x 2 rows
        #pragma unroll
        for (int e = 0; e < EK; e += 4) {
            unsigned long long wv0[9], wv1[9];
            #pragma unroll
            for (int c = 0; c < 9; c++) {
                ulonglong2 w2 = *reinterpret_cast<const ulonglong2*>(
                    &ws[(cgrp * 9 + c) * WS_STRIDE + e]);  // broadcast LDS.128
                wv0[c] = w2.x;
                wv1[c] = w2.y;
            }
            #pragma unroll
            for (int i = 0; i < 2; i++) {
                int row = rgrp + 32 * i;
                const unsigned long long* xr =
                    reinterpret_cast<const unsigned long long*>(&xs[row * XS_STRIDE]);
                int r4 = row & 15;
                unsigned long long xa = xr[(e / 2) ^ r4];
                unsigned long long xb = xr[(e / 2 + 1) ^ r4];
                #pragma unroll
                for (int c = 0; c < 9; c++) {
                    acc[i][c] = ffma2(xa, wv0[c], acc[i][c]);
                    acc[i][c] = ffma2(xb, wv1[c], acc[i][c]);
                }
            }
        }
        __syncthreads();
    }

    // ---- reduce f32x2 pairs, stage into smem (reuse xs), write coalesced
    #pragma unroll
    for (int i = 0; i < 2; i++) {
        int row = rgrp + 32 * i;
        #pragma unroll
        for (int c = 0; c < 9; c++) {
            float lo, hi;
            asm("mov.b64 {%0,%1}, %2;" : "=f"(lo), "=f"(hi) : "l"(acc[i][c]));
            xs[row * NWV + cgrp * 9 + c] = lo + hi;
        }
    }
    __syncthreads();

    float* qdst = g_Q + (size_t)rowBase * NWV;   // block's 64*18 region is contiguous
    #pragma unroll
    for (int t = tid; t < TILE_ROWS * NWV / 4; t += THREADS1) {
        *reinterpret_cast<float4*>(qdst + t * 4) =
            *reinterpret_cast<const float4*>(&xs[t * 4]);
    }
}

// ---------------------------------------------------------------------------
// Kernel 2: shift-combine + activations
//   s_k[l] = sum_j Q[l + j - p][col_j];  out_k = tanh(sigmoid(s_k+ab)*Q[.,cw_k]+cb)
// ---------------------------------------------------------------------------
__global__ void combine_kernel(
    const float* __restrict__ ab3, const float* __restrict__ cb3,
    const float* __restrict__ ab5, const float* __restrict__ cb5,
    const float* __restrict__ ab7, const float* __restrict__ cb7,
    float* __restrict__ out)
{
    int row = blockIdx.x * blockDim.x + threadIdx.x;
    if (row >= NROWS) return;
    int l = row % LL;
    const float* q = g_Q + (size_t)row * NWV;

    float s3 = 0.f, s5 = 0.f, s7 = 0.f;
    #pragma unroll
    for (int j = 0; j < 3; j++) {
        int d = j - 1, nl = l + d;
        if (nl >= 0 && nl < LL) s3 += q[(long)d * NWV + j];
    }
    #pragma unroll
    for (int j = 0; j < 5; j++) {
        int d = j - 2, nl = l + d;
        if (nl >= 0 && nl < LL) s5 += q[(long)d * NWV + 3 + j];
    }
    #pragma unroll
    for (int j = 0; j < 7; j++) {
        int d = j - 3, nl = l + d;
        if (nl >= 0 && nl < LL) s7 += q[(long)d * NWV + 8 + j];
    }

    float d3 = q[15], d5 = q[16], d7 = q[17];
    float sc3 = 1.f / (1.f + expf(-(s3 + ab3[0])));
    float sc5 = 1.f / (1.f + expf(-(s5 + ab5[0])));
    float sc7 = 1.f / (1.f + expf(-(s7 + ab7[0])));

    out[row]             = tanhf(sc3 * d3 + cb3[0]);
    out[NROWS + row]     = tanhf(sc5 * d5 + cb5[0]);
    out[2 * NROWS + row] = tanhf(sc7 * d7 + cb7[0]);
}

// ---------------------------------------------------------------------------
extern "C" void kernel_launch(void* const* d_in, const int* in_sizes, int n_in,
                              void* d_out, int out_size) {
    const float* x   = (const float*)d_in[0];
    const float* aw3 = (const float*)d_in[1];
    const float* ab3 = (const float*)d_in[2];
    const float* cw3 = (const float*)d_in[3];
    const float* cb3 = (const float*)d_in[4];
    const float* aw5 = (const float*)d_in[5];
    const float* ab5 = (const float*)d_in[6];
    const float* cw5 = (const float*)d_in[7];
    const float* cb5 = (const float*)d_in[8];
    const float* aw7 = (const float*)d_in[9];
    const float* ab7 = (const float*)d_in[10];
    const float* cw7 = (const float*)d_in[11];
    const float* cb7 = (const float*)d_in[12];
    float* out = (float*)d_out;

    dots_kernel<<<NROWS / TILE_ROWS, THREADS1>>>(x, aw3, aw5, aw7, cw3, cw5, cw7);
    combine_kernel<<<(NROWS + 255) / 256, 256>>>(ab3, cb3, ab5, cb5, ab7, cb7, out);
}